// round 8
// baseline (speedup 1.0000x reference)
#include <cuda_runtime.h>
#include <cuda_fp16.h>

#define N_NODES 50000
#define N_EDGES 1600000
#define BATCH   4
#define T_STEPS 50
#define DT      0.02f

#define NBLK    148
#define NTHR    1024
#define ROWS_PER_BLK 338                     // ceil(50000/148)
#define GROUPS  (NTHR / 8)                   // 128 row-groups (8 lanes each)
#define NPASS   3                            // ceil(338/128)

#define NQTR      4
#define QTR       12500                      // nodes per quarter
#define QTR_BYTES (QTR * 8)                  // 100000 B (fp16x4 per node)

// SMEM layout (dynamic, byte offsets)
#define SM_BUF0    0
#define SM_BUF1    QTR_BYTES
#define SM_ACC     (2 * QTR_BYTES)                       // float[BATCH][ROWS_PER_BLK]
#define SM_ACC_B   (BATCH * ROWS_PER_BLK * 4)            // 5408
#define SM_STG     (SM_ACC + SM_ACC_B)                   // half[ROWS_PER_BLK][BATCH]
#define SM_STG_B   (ROWS_PER_BLK * BATCH * 2)            // 2704
#define SM_BND     (SM_STG + SM_STG_B)                   // int[NPASS*GROUPS*5]
#define SM_BND_B   (NPASS * GROUPS * 5 * 4)              // 7680
#define SM_MBAR    (SM_BND + SM_BND_B)                   // 4 mbarriers (8B each)
#define SMEM_TOTAL (SM_MBAR + 64)

// ---------------- static scratch (no allocations allowed) ----------------
__device__ int   g_hist4[NQTR * N_NODES];
__device__ int   g_qstart[NQTR * N_NODES + 1];
__device__ int   g_cursor4[NQTR * N_NODES];
__device__ int2  g_edges[N_EDGES];            // (local col within quarter, weight bits)
__device__ uint2 g_ratebuf[2][N_NODES];       // ping-pong fp16x4 rates (8B/node)
__device__ float g_alpha[N_NODES];
__device__ unsigned          g_bar_count;
__device__ volatile unsigned g_bar_sense;

// ---------------- small PTX helpers ----------------
__device__ __forceinline__ unsigned smem_u32(const void* p) {
    unsigned a;
    asm("{ .reg .u64 t; cvta.to.shared.u64 t, %1; cvt.u32.u64 %0, t; }" : "=r"(a) : "l"(p));
    return a;
}
__device__ __forceinline__ void mbar_init(unsigned mbar, unsigned count) {
    asm volatile("mbarrier.init.shared.b64 [%0], %1;" :: "r"(mbar), "r"(count) : "memory");
}
__device__ __forceinline__ void mbar_expect_tx(unsigned mbar, unsigned bytes) {
    asm volatile("mbarrier.arrive.expect_tx.shared.b64 _, [%0], %1;" :: "r"(mbar), "r"(bytes) : "memory");
}
__device__ __forceinline__ void bulk_g2s(unsigned dst_smem, const void* src, unsigned bytes, unsigned mbar) {
    asm volatile("cp.async.bulk.shared::cta.global.mbarrier::complete_tx::bytes [%0], [%1], %2, [%3];"
                 :: "r"(dst_smem), "l"(src), "r"(bytes), "r"(mbar) : "memory");
}
__device__ __forceinline__ void mbar_wait(unsigned mbar, unsigned parity) {
    unsigned done;
    do {
        asm volatile(
            "{\n\t.reg .pred p;\n\t"
            "mbarrier.try_wait.parity.shared::cta.b64 p, [%1], %2, 0x989680;\n\t"
            "selp.b32 %0, 1, 0, p;\n\t}"
            : "=r"(done) : "r"(mbar), "r"(parity) : "memory");
    } while (!done);
}

// ---------------- preprocessing ----------------

__global__ void init_kernel(const float* __restrict__ bias,
                            const float* __restrict__ tau) {
    int n = blockIdx.x * blockDim.x + threadIdx.x;
    if (n == 0) { g_bar_count = 0; g_bar_sense = 0; }
    if (n >= N_NODES) return;
#pragma unroll
    for (int q = 0; q < NQTR; q++) g_hist4[n * NQTR + q] = 0;
    float b = bias[n];
    float r = fmaxf(b, 0.0f);
    unsigned hb = (unsigned)__half_as_ushort(__float2half_rn(r));
    unsigned u  = hb | (hb << 16);
    g_ratebuf[0][n] = make_uint2(u, u);
    float tt = fmaxf(tau[n], DT);
    g_alpha[n] = DT / tt;
}

__global__ void hist_kernel(const int* __restrict__ src,
                            const int* __restrict__ tgt) {
    int e = blockIdx.x * blockDim.x + threadIdx.x;
    if (e >= N_EDGES) return;
    int q = src[e] / QTR;
    atomicAdd(&g_hist4[tgt[e] * NQTR + q], 1);
}

// Single-block exclusive scan over 200K (row,quarter) bins
__global__ void scan_kernel() {
    __shared__ int s[1024];
    int tid = threadIdx.x;
    const int NB = NQTR * N_NODES;           // 200000
    const int chunk = (NB + 1023) / 1024;    // 196
    int beg = tid * chunk;
    int end = min(beg + chunk, NB);
    int sum = 0;
    for (int i = beg; i < end; i++) sum += g_hist4[i];
    s[tid] = sum;
    __syncthreads();
    for (int off = 1; off < 1024; off <<= 1) {
        int v = (tid >= off) ? s[tid - off] : 0;
        __syncthreads();
        s[tid] += v;
        __syncthreads();
    }
    int prefix = (tid > 0) ? s[tid - 1] : 0;
    for (int i = beg; i < end; i++) {
        g_qstart[i]  = prefix;
        g_cursor4[i] = prefix;
        prefix += g_hist4[i];
    }
    if (tid == 0) g_qstart[NB] = s[1023];
}

// Counting-sort edges into CSR by (target, source-quarter); store local col.
__global__ void scatter_kernel(const int*   __restrict__ src,
                               const int*   __restrict__ tgt,
                               const float* __restrict__ sign,
                               const float* __restrict__ cnt,
                               const float* __restrict__ str) {
    int e = blockIdx.x * blockDim.x + threadIdx.x;
    if (e >= N_EDGES) return;
    float w = sign[e] * fmaxf(cnt[e], 0.0f) * fmaxf(str[e], 0.0f);
    int s = src[e];
    int q = s / QTR;
    int pos = atomicAdd(&g_cursor4[tgt[e] * NQTR + q], 1);
    g_edges[pos] = make_int2(s - q * QTR, __float_as_int(w));
}

// ---------------- software grid barrier (all NBLK blocks resident) ------
__device__ __forceinline__ void grid_barrier(unsigned target) {
    __syncthreads();
    if (threadIdx.x == 0) {
        __threadfence();
        unsigned a = atomicAdd(&g_bar_count, 1);
        if (a == NBLK - 1) {
            g_bar_count = 0;
            __threadfence();
            g_bar_sense = target;
        } else {
            while (g_bar_sense != target) { }
            __threadfence();
        }
    }
    __syncthreads();
}

// ---------------- persistent kernel: all 50 steps, quarter-pipelined ----
// Per step, each block accumulates its 338 rows over 4 source-quarters.
// The active quarter's fp16x4 rates live in local SMEM (pure-LDS gather,
// ~5cyc/warp vs 66cyc for random LDG). Quarter q+2 streams in via
// cp.async.bulk while quarter q is gathered (double-buffered).
__global__ void __launch_bounds__(NTHR, 1)
persist_kernel(const float* __restrict__ x,
               float*       __restrict__ out,
               const float* __restrict__ bias) {
    extern __shared__ unsigned char smem[];
    float*  s_acc = (float*)(smem + SM_ACC);
    __half* s_stg = (__half*)(smem + SM_STG);
    int*    s_bnd = (int*)(smem + SM_BND);

    unsigned mbar[NQTR];
#pragma unroll
    for (int q = 0; q < NQTR; q++) mbar[q] = smem_u32(smem + SM_MBAR + 8 * q);
    unsigned buf_u32[2] = { smem_u32(smem + SM_BUF0), smem_u32(smem + SM_BUF1) };

    int tid = threadIdx.x;
    int sub = tid & 7;
    int grp = tid >> 3;
    int rowbase = blockIdx.x * ROWS_PER_BLK;
    int nrows   = min(ROWS_PER_BLK, N_NODES - rowbase);

    // quarter bounds table: [pass][group][0..4]
    for (int idx = tid; idx < NPASS * GROUPS * 5; idx += NTHR) {
        int p = idx / (GROUPS * 5);
        int r = idx % (GROUPS * 5);
        int g = r / 5, k = r % 5;
        int rl = p * GROUPS + g;
        int v = 0;
        if (rl < nrows) v = g_qstart[(rowbase + rl) * NQTR + k];
        s_bnd[idx] = v;
    }

    // epilogue slots: thread owns up to 2 (row,batch); coalesced x/out
    int   er[2] = {-1, -1}, eb[2] = {0, 0};
    float ev[2] = {0.f, 0.f}, ea[2] = {0.f, 0.f}, ebi[2] = {0.f, 0.f};
#pragma unroll
    for (int p = 0; p < 2; p++) {
        int slot = p * NTHR + tid;
        if (slot < ROWS_PER_BLK * BATCH) {
            int b  = slot / ROWS_PER_BLK;
            int rl = slot % ROWS_PER_BLK;
            if (rl < nrows) {
                int row = rowbase + rl;
                er[p] = rl; eb[p] = b;
                ebi[p] = bias[row];
                ea[p]  = g_alpha[row];
                ev[p]  = ebi[p];                 // v0 = bias
            }
        }
    }

    if (tid == 0) {
#pragma unroll
        for (int q = 0; q < NQTR; q++) mbar_init(mbar[q], 1);
    }
    __syncthreads();

    // prime pipeline: quarters 0,1 of step 0 from buffer 0
    if (tid == 0) {
#pragma unroll
        for (int q = 0; q < 2; q++) {
            mbar_expect_tx(mbar[q], QTR_BYTES);
            bulk_g2s(buf_u32[q], (const char*)&g_ratebuf[0][q * QTR], QTR_BYTES, mbar[q]);
        }
    }

    for (int t = 0; t < T_STEPS; t++) {
        const uint2* gbuf = g_ratebuf[t & 1];
        float4 accs[NPASS];
#pragma unroll
        for (int p = 0; p < NPASS; p++) accs[p] = make_float4(0.f, 0.f, 0.f, 0.f);

        for (int q = 0; q < NQTR; q++) {
            mbar_wait(mbar[q], (unsigned)(t & 1));
            const unsigned char* sb = smem + (q & 1) * QTR_BYTES;
#pragma unroll
            for (int p = 0; p < NPASS; p++) {
                int bnd_base = (p * GROUPS + grp) * 5 + q;
                int qb = s_bnd[bnd_base];
                int qe = s_bnd[bnd_base + 1];
                float4 acc = accs[p];
                for (int e = qb + sub; e < qe; e += 8) {
                    int2 ed = __ldg(&g_edges[e]);
                    uint2 rv = *(const uint2*)(sb + (unsigned)ed.x * 8u);
                    float2 lo = __half22float2(*(const __half2*)&rv.x);
                    float2 hi = __half22float2(*(const __half2*)&rv.y);
                    float w = __int_as_float(ed.y);
                    acc.x = fmaf(w, lo.x, acc.x);
                    acc.y = fmaf(w, lo.y, acc.y);
                    acc.z = fmaf(w, hi.x, acc.z);
                    acc.w = fmaf(w, hi.y, acc.w);
                }
                accs[p] = acc;
            }
            __syncthreads();   // all warps done reading buf[q&1]
            if (q < 2 && tid == 0) {
                int qq = q + 2;
                mbar_expect_tx(mbar[qq], QTR_BYTES);
                bulk_g2s(buf_u32[q & 1], (const char*)&gbuf[qq * QTR], QTR_BYTES, mbar[qq]);
            }
        }

        // reduce 8-lane groups, stash per-row sums
#pragma unroll
        for (int p = 0; p < NPASS; p++) {
            float4 acc = accs[p];
#pragma unroll
            for (int off = 4; off; off >>= 1) {
                acc.x += __shfl_down_sync(0xffffffffu, acc.x, off);
                acc.y += __shfl_down_sync(0xffffffffu, acc.y, off);
                acc.z += __shfl_down_sync(0xffffffffu, acc.z, off);
                acc.w += __shfl_down_sync(0xffffffffu, acc.w, off);
            }
            int rl = p * GROUPS + grp;
            if (sub == 0 && rl < nrows) {
                s_acc[0 * ROWS_PER_BLK + rl] = acc.x;
                s_acc[1 * ROWS_PER_BLK + rl] = acc.y;
                s_acc[2 * ROWS_PER_BLK + rl] = acc.z;
                s_acc[3 * ROWS_PER_BLK + rl] = acc.w;
            }
        }
        __syncthreads();

        // epilogue: Euler update, coalesced x/out, stage fp16 rates
#pragma unroll
        for (int p = 0; p < 2; p++) {
            if (er[p] >= 0) {
                int row = rowbase + er[p];
                int idx = (eb[p] * T_STEPS + t) * N_NODES + row;
                float sum = s_acc[eb[p] * ROWS_PER_BLK + er[p]];
                float v = ev[p];
                float vn = v + ea[p] * (ebi[p] + sum + x[idx] - v);
                ev[p] = vn;
                float rl = fmaxf(vn, 0.f);
                out[idx] = rl;
                s_stg[er[p] * BATCH + eb[p]] = __float2half_rn(rl);
            }
        }
        __syncthreads();

        if (t + 1 < T_STEPS) {
            // publish new rates, sync grid, prime quarters 0,1 of next step
            uint2* gout = g_ratebuf[(t + 1) & 1];
            for (int rl = tid; rl < nrows; rl += NTHR)
                gout[rowbase + rl] = *(const uint2*)&s_stg[rl * BATCH];
            grid_barrier((unsigned)(t + 1));
            if (tid == 0) {
                const uint2* gnext = g_ratebuf[(t + 1) & 1];
#pragma unroll
                for (int q = 0; q < 2; q++) {
                    mbar_expect_tx(mbar[q], QTR_BYTES);
                    bulk_g2s(buf_u32[q], (const char*)&gnext[q * QTR], QTR_BYTES, mbar[q]);
                }
            }
        }
    }
}

// ---------------- launch ----------------
extern "C" void kernel_launch(void* const* d_in, const int* in_sizes, int n_in,
                              void* d_out, int out_size) {
    const float* x    = (const float*)d_in[0];
    const float* bias = (const float*)d_in[1];
    const float* tau  = (const float*)d_in[2];
    const float* sign = (const float*)d_in[3];
    const float* cnt  = (const float*)d_in[4];
    const float* str  = (const float*)d_in[5];
    const int*   src  = (const int*)  d_in[6];
    const int*   tgt  = (const int*)  d_in[7];
    float*       out  = (float*)d_out;

    cudaFuncSetAttribute(persist_kernel,
                         cudaFuncAttributeMaxDynamicSharedMemorySize,
                         SMEM_TOTAL);

    init_kernel<<<(N_NODES + 255) / 256, 256>>>(bias, tau);
    hist_kernel<<<(N_EDGES + 255) / 256, 256>>>(src, tgt);
    scan_kernel<<<1, 1024>>>();
    scatter_kernel<<<(N_EDGES + 255) / 256, 256>>>(src, tgt, sign, cnt, str);

    persist_kernel<<<NBLK, NTHR, SMEM_TOTAL>>>(x, out, bias);
}

// round 10
// speedup vs baseline: 1.0180x; 1.0180x over previous
#include <cuda_runtime.h>

#define N_NODES 50000
#define N_EDGES 1600000
#define BATCH   4
#define T_STEPS 50
#define DT      0.02f

#define NBLK    148
#define NTHR    1024
#define ROWS_PER_BLK 338                     // ceil(50000/148)
#define GROUPS  (NTHR / 8)                   // 128 node-groups (8 lanes each)
#define NPASS   3                            // ceil(338/128)

// ---------------- static scratch (no allocations allowed) ----------------
__device__ int    g_hist[N_NODES];
__device__ int    g_col_start[N_NODES + 1];  // CSC: edges sorted by SOURCE
__device__ int    g_cursor[N_NODES];
__device__ int2   g_edges[N_EDGES];          // (target, weight bits)
__device__ float4 g_acc[2][N_NODES];         // ping-pong synaptic accumulators
__device__ float  g_alpha[N_NODES];
__device__ unsigned          g_bar_count;
__device__ volatile unsigned g_bar_sense;

// vector reduction: 16B fire-and-forget atomic add (sm_90+)
__device__ __forceinline__ void red_add_v4(float4* addr, float a, float b,
                                           float c, float d) {
    asm volatile("red.global.add.v4.f32 [%0], {%1, %2, %3, %4};"
                 :: "l"(addr), "f"(a), "f"(b), "f"(c), "f"(d) : "memory");
}

// ---------------- preprocessing ----------------

__global__ void init_kernel(const float* __restrict__ tau) {
    int n = blockIdx.x * blockDim.x + threadIdx.x;
    if (n == 0) { g_bar_count = 0; g_bar_sense = 0; }
    if (n >= N_NODES) return;
    g_hist[n] = 0;
    g_acc[0][n] = make_float4(0.f, 0.f, 0.f, 0.f);
    g_acc[1][n] = make_float4(0.f, 0.f, 0.f, 0.f);
    float tt = fmaxf(tau[n], DT);
    g_alpha[n] = DT / tt;
}

__global__ void hist_kernel(const int* __restrict__ src) {
    int e = blockIdx.x * blockDim.x + threadIdx.x;
    if (e >= N_EDGES) return;
    atomicAdd(&g_hist[src[e]], 1);
}

// Single-block exclusive scan over 50K source bins
__global__ void scan_kernel() {
    __shared__ int s[1024];
    int tid = threadIdx.x;
    const int chunk = (N_NODES + 1023) / 1024;
    int beg = tid * chunk;
    int end = min(beg + chunk, N_NODES);
    int sum = 0;
    for (int i = beg; i < end; i++) sum += g_hist[i];
    s[tid] = sum;
    __syncthreads();
    for (int off = 1; off < 1024; off <<= 1) {
        int v = (tid >= off) ? s[tid - off] : 0;
        __syncthreads();
        s[tid] += v;
        __syncthreads();
    }
    int prefix = (tid > 0) ? s[tid - 1] : 0;
    for (int i = beg; i < end; i++) {
        g_col_start[i] = prefix;
        g_cursor[i]    = prefix;
        prefix += g_hist[i];
    }
    if (tid == 0) g_col_start[N_NODES] = s[1023];
}

// Counting-sort edges into CSC (by source), fused (target, weight) record.
__global__ void sort_kernel(const int*   __restrict__ src,
                            const int*   __restrict__ tgt,
                            const float* __restrict__ sign,
                            const float* __restrict__ cnt,
                            const float* __restrict__ str) {
    int e = blockIdx.x * blockDim.x + threadIdx.x;
    if (e >= N_EDGES) return;
    float w = sign[e] * fmaxf(cnt[e], 0.0f) * fmaxf(str[e], 0.0f);
    int pos = atomicAdd(&g_cursor[src[e]], 1);
    g_edges[pos] = make_int2(tgt[e], __float_as_int(w));
}

// ---------------- software grid barrier with release/acquire ------------
// Every thread fences (release of its REDs) before arrival; acquire after.
__device__ __forceinline__ void grid_barrier(unsigned target) {
    __threadfence();              // make this thread's REDs visible (release)
    __syncthreads();
    if (threadIdx.x == 0) {
        unsigned a = atomicAdd(&g_bar_count, 1);
        if (a == NBLK - 1) {
            g_bar_count = 0;
            __threadfence();
            g_bar_sense = target;
        } else {
            while (g_bar_sense != target) { }
            __threadfence();      // acquire
        }
    }
    __syncthreads();
}

// ---------------- persistent kernel: owner-computes scatter --------------
// Block owns nodes [rowbase, rowbase+338): keeps their v in registers,
// rates in SMEM. Per step: push w*rate along outgoing edges via
// red.global.add.v4.f32 into g_acc[t&1]; grid barrier; Euler update reads
// own acc entries, zeroes them (safe: next scatter into this buffer is two
// barriers away), writes out + next rates.
__global__ void __launch_bounds__(NTHR, 1)
persist_kernel(const float* __restrict__ x,
               float*       __restrict__ out,
               const float* __restrict__ bias) {
    __shared__ float4 s_rate[ROWS_PER_BLK];

    int tid = threadIdx.x;
    int sub = tid & 7;
    int grp = tid >> 3;
    int rowbase = blockIdx.x * ROWS_PER_BLK;
    int nrows   = min(ROWS_PER_BLK, max(0, N_NODES - rowbase));

    // scatter-phase bounds (CSC) per pass, loaded once
    int beg[NPASS], end[NPASS], rloc[NPASS];
#pragma unroll
    for (int p = 0; p < NPASS; p++) {
        int rl = p * GROUPS + grp;
        bool ok = rl < nrows;
        int node = rowbase + rl;
        beg[p]  = ok ? g_col_start[node]     : 0;
        end[p]  = ok ? g_col_start[node + 1] : 0;
        rloc[p] = ok ? rl : -1;
    }

    // epilogue slots: thread owns up to 2 (node,batch) components; coalesced
    int   er[2] = {-1, -1}, eb[2] = {0, 0};
    float ev[2] = {0.f, 0.f}, ea[2] = {0.f, 0.f}, ebi[2] = {0.f, 0.f};
#pragma unroll
    for (int p = 0; p < 2; p++) {
        int slot = p * NTHR + tid;
        if (slot < ROWS_PER_BLK * BATCH) {
            int b  = slot / ROWS_PER_BLK;
            int rl = slot % ROWS_PER_BLK;
            if (rl < nrows) {
                int node = rowbase + rl;
                er[p] = rl; eb[p] = b;
                ebi[p] = bias[node];
                ea[p]  = g_alpha[node];
                ev[p]  = ebi[p];                     // v0 = bias
            }
        }
    }

    // initial rates = relu(bias)
    for (int rl = tid; rl < nrows; rl += NTHR) {
        float r = fmaxf(bias[rowbase + rl], 0.f);
        s_rate[rl] = make_float4(r, r, r, r);
    }
    __syncthreads();

    for (int t = 0; t < T_STEPS; t++) {
        float4* __restrict__ acc = g_acc[t & 1];

        // ---- scatter: push w * rate along outgoing edges ----
#pragma unroll
        for (int p = 0; p < NPASS; p++) {
            if (rloc[p] >= 0) {
                float4 r = s_rate[rloc[p]];          // LDS broadcast in group
                for (int e = beg[p] + sub; e < end[p]; e += 8) {
                    int2 ed = __ldg(&g_edges[e]);
                    float w = __int_as_float(ed.y);
                    red_add_v4(&acc[ed.x], w * r.x, w * r.y, w * r.z, w * r.w);
                }
            }
        }

        grid_barrier((unsigned)(t + 1));             // all contributions in

        // ---- update: Euler step on own nodes, zero own acc entries ----
        float* accf = (float*)acc;
#pragma unroll
        for (int p = 0; p < 2; p++) {
            if (er[p] >= 0) {
                int node = rowbase + er[p];
                int comp = node * 4 + eb[p];
                float sum = accf[comp];
                accf[comp] = 0.f;                    // reuse at step t+2
                int idx = (eb[p] * T_STEPS + t) * N_NODES + node;
                float v = ev[p];
                float vn = v + ea[p] * (ebi[p] + sum + x[idx] - v);
                ev[p] = vn;
                float rl = fmaxf(vn, 0.f);
                out[idx] = rl;
                ((float*)&s_rate[er[p]])[eb[p]] = rl;
            }
        }
        __syncthreads();                             // s_rate ready for t+1
    }
}

// ---------------- launch ----------------
extern "C" void kernel_launch(void* const* d_in, const int* in_sizes, int n_in,
                              void* d_out, int out_size) {
    const float* x    = (const float*)d_in[0];
    const float* bias = (const float*)d_in[1];
    const float* tau  = (const float*)d_in[2];
    const float* sign = (const float*)d_in[3];
    const float* cnt  = (const float*)d_in[4];
    const float* str  = (const float*)d_in[5];
    const int*   src  = (const int*)  d_in[6];
    const int*   tgt  = (const int*)  d_in[7];
    float*       out  = (float*)d_out;

    init_kernel<<<(N_NODES + 255) / 256, 256>>>(tau);
    hist_kernel<<<(N_EDGES + 255) / 256, 256>>>(src);
    scan_kernel<<<1, 1024>>>();
    sort_kernel<<<(N_EDGES + 255) / 256, 256>>>(src, tgt, sign, cnt, str);

    persist_kernel<<<NBLK, NTHR>>>(x, out, bias);
}

// round 11
// speedup vs baseline: 1.0943x; 1.0750x over previous
#include <cuda_runtime.h>
#include <cuda_fp16.h>

#define N_NODES 50000
#define N_EDGES 1600000
#define BATCH   4
#define T_STEPS 50
#define DT      0.02f

#define NBLK    148
#define NTHR    1024

#define NQ      4
#define QTR     12500                        // nodes per quarter
#define QTR_BYTES (QTR * 8)                  // 100000 (fp16x4 per node)
#define NRANGE  37                           // 148 / 4
#define RPB     1352                         // gather rows per range (37*1352=50024)
#define URPB    338                          // update rows per block (148*338=50024)

// dynamic SMEM layout
#define SM_RATES 0                           // uint2[QTR] = 100000 B
#define SM_BND   QTR_BYTES                   // int[RPB+1] = 5412 B
#define SM_MBAR  105424
#define SMEM_TOTAL (SM_MBAR + 16)

// ---------------- static scratch (no allocations allowed) ----------------
__device__ int   g_hist2[NQ * N_NODES];
__device__ int   g_qstart[NQ * N_NODES + 1];  // CSR by key = q*N + target
__device__ int   g_cursor2[NQ * N_NODES];
__device__ int2  g_edges[N_EDGES];            // (col local to quarter, weight bits)
__device__ float4 g_part[NQ][N_NODES];        // per-quarter partial row sums
__device__ __align__(16) uint2 g_ratebuf[2][N_NODES];  // ping-pong fp16x4 rates
__device__ float g_alpha[N_NODES];
__device__ unsigned          g_bar_count;
__device__ volatile unsigned g_bar_sense;

// ---------------- PTX helpers ----------------
__device__ __forceinline__ unsigned smem_u32(const void* p) {
    unsigned a;
    asm("{ .reg .u64 t; cvta.to.shared.u64 t, %1; cvt.u32.u64 %0, t; }" : "=r"(a) : "l"(p));
    return a;
}
__device__ __forceinline__ void mbar_init(unsigned mbar, unsigned count) {
    asm volatile("mbarrier.init.shared.b64 [%0], %1;" :: "r"(mbar), "r"(count) : "memory");
}
__device__ __forceinline__ void mbar_expect_tx(unsigned mbar, unsigned bytes) {
    asm volatile("mbarrier.arrive.expect_tx.shared.b64 _, [%0], %1;" :: "r"(mbar), "r"(bytes) : "memory");
}
__device__ __forceinline__ void bulk_g2s(unsigned dst, const void* src, unsigned bytes, unsigned mbar) {
    asm volatile("cp.async.bulk.shared::cta.global.mbarrier::complete_tx::bytes [%0], [%1], %2, [%3];"
                 :: "r"(dst), "l"(src), "r"(bytes), "r"(mbar) : "memory");
}
__device__ __forceinline__ void mbar_wait(unsigned mbar, unsigned parity) {
    unsigned done;
    do {
        asm volatile(
            "{\n\t.reg .pred p;\n\t"
            "mbarrier.try_wait.parity.shared::cta.b64 p, [%1], %2, 0x989680;\n\t"
            "selp.b32 %0, 1, 0, p;\n\t}"
            : "=r"(done) : "r"(mbar), "r"(parity) : "memory");
    } while (!done);
}
__device__ __forceinline__ float4 ldcg_f4(const float4* p) {
    float4 v;
    asm volatile("ld.global.cg.v4.f32 {%0,%1,%2,%3}, [%4];"
                 : "=f"(v.x), "=f"(v.y), "=f"(v.z), "=f"(v.w) : "l"(p));
    return v;
}

// ---------------- preprocessing ----------------

__global__ void init_kernel(const float* __restrict__ bias,
                            const float* __restrict__ tau) {
    int n = blockIdx.x * blockDim.x + threadIdx.x;
    if (n == 0) { g_bar_count = 0; g_bar_sense = 0; }
    if (n >= N_NODES) return;
#pragma unroll
    for (int q = 0; q < NQ; q++) g_hist2[q * N_NODES + n] = 0;
    float b = bias[n];
    float r = fmaxf(b, 0.0f);
    unsigned hb = (unsigned)__half_as_ushort(__float2half_rn(r));
    unsigned u  = hb | (hb << 16);
    g_ratebuf[0][n] = make_uint2(u, u);
    float tt = fmaxf(tau[n], DT);
    g_alpha[n] = DT / tt;
}

__global__ void hist_kernel(const int* __restrict__ src,
                            const int* __restrict__ tgt) {
    int e = blockIdx.x * blockDim.x + threadIdx.x;
    if (e >= N_EDGES) return;
    int q = src[e] / QTR;
    atomicAdd(&g_hist2[q * N_NODES + tgt[e]], 1);
}

// Single-block exclusive scan over 200K (quarter,row) bins
__global__ void scan_kernel() {
    __shared__ int s[1024];
    int tid = threadIdx.x;
    const int NB = NQ * N_NODES;             // 200000
    const int chunk = (NB + 1023) / 1024;    // 196
    int beg = tid * chunk;
    int end = min(beg + chunk, NB);
    int sum = 0;
    for (int i = beg; i < end; i++) sum += g_hist2[i];
    s[tid] = sum;
    __syncthreads();
    for (int off = 1; off < 1024; off <<= 1) {
        int v = (tid >= off) ? s[tid - off] : 0;
        __syncthreads();
        s[tid] += v;
        __syncthreads();
    }
    int prefix = (tid > 0) ? s[tid - 1] : 0;
    for (int i = beg; i < end; i++) {
        g_qstart[i]  = prefix;
        g_cursor2[i] = prefix;
        prefix += g_hist2[i];
    }
    if (tid == 0) g_qstart[NB] = s[1023];
}

// Counting-sort edges by key (source-quarter, target); store quarter-local col.
__global__ void sort_kernel(const int*   __restrict__ src,
                            const int*   __restrict__ tgt,
                            const float* __restrict__ sign,
                            const float* __restrict__ cnt,
                            const float* __restrict__ str) {
    int e = blockIdx.x * blockDim.x + threadIdx.x;
    if (e >= N_EDGES) return;
    float w = sign[e] * fmaxf(cnt[e], 0.0f) * fmaxf(str[e], 0.0f);
    int s = src[e];
    int q = s / QTR;
    int pos = atomicAdd(&g_cursor2[q * N_NODES + tgt[e]], 1);
    g_edges[pos] = make_int2(s - q * QTR, __float_as_int(w));
}

// ---------------- software grid barrier (release/acquire) ----------------
__device__ __forceinline__ void grid_barrier(unsigned target) {
    __threadfence();
    __syncthreads();
    if (threadIdx.x == 0) {
        unsigned a = atomicAdd(&g_bar_count, 1);
        if (a == NBLK - 1) {
            g_bar_count = 0;
            __threadfence();
            g_bar_sense = target;
        } else {
            while (g_bar_sense != target) { }
            __threadfence();
        }
    }
    __syncthreads();
}

// ---------------- persistent split-K kernel --------------------------------
// Block b = (range rr = b>>2, quarter q = b&3).
//  Phase A: partial SpMV of rows [rr*RPB,+RPB) restricted to sources in
//           quarter q, whose fp16x4 rates sit in SMEM (pure LDS gather).
//           Writes float4 partials to g_part[q][row].      barrier
//  Phase B: block owns rows [b*URPB,+URPB): sums 4 partials, Euler update
//           (v in registers), writes out + fp16x4 rates.   barrier
//  Refill:  cp.async.bulk of own quarter of next rates (100KB, ~1us).
__global__ void __launch_bounds__(NTHR, 1)
persist_kernel(const float* __restrict__ x,
               float*       __restrict__ out,
               const float* __restrict__ bias) {
    extern __shared__ unsigned char smem[];
    const uint2* s_rates = (const uint2*)(smem + SM_RATES);
    int*         s_bnd   = (int*)(smem + SM_BND);
    unsigned mbar  = smem_u32(smem + SM_MBAR);
    unsigned sdest = smem_u32(smem + SM_RATES);

    int tid = threadIdx.x;
    int q   = blockIdx.x & 3;
    int rr  = blockIdx.x >> 2;
    int row0   = rr * RPB;
    int nrows  = min(RPB, max(0, N_NODES - row0));

    // segment bounds for (q, row0..row0+nrows) — contiguous keys, loaded once
    for (int i = tid; i <= nrows; i += NTHR)
        s_bnd[i] = g_qstart[q * N_NODES + row0 + i];

    // phase-B state: thread t owns update row urow0+t (v in registers)
    int urow0 = blockIdx.x * URPB;
    int un    = min(URPB, max(0, N_NODES - urow0));
    float4 v  = make_float4(0.f, 0.f, 0.f, 0.f);
    float  my_a = 0.f, my_b = 0.f;
    int    myrow = -1;
    if (tid < un) {
        myrow = urow0 + tid;
        my_b  = bias[myrow];
        my_a  = g_alpha[myrow];
        v = make_float4(my_b, my_b, my_b, my_b);        // v0 = bias
    }

    if (tid == 0) mbar_init(mbar, 1);
    __syncthreads();
    if (tid == 0) {                                     // prime: quarter of rates_0
        mbar_expect_tx(mbar, QTR_BYTES);
        bulk_g2s(sdest, (const char*)&g_ratebuf[0][q * QTR], QTR_BYTES, mbar);
    }

    int sub = tid & 3;          // 4 lanes per row
    int grp = tid >> 2;         // 256 row-groups

    const long long TN = (long long)T_STEPS * N_NODES;

    for (int t = 0; t < T_STEPS; t++) {
        mbar_wait(mbar, (unsigned)(t & 1));             // quarter data ready

        // ---- Phase A: partial gather over own quarter ----
#pragma unroll
        for (int p = 0; p < 6; p++) {                   // 6*256 = 1536 >= 1352
            int rl = p * 256 + grp;
            float4 acc = make_float4(0.f, 0.f, 0.f, 0.f);
            bool ok = rl < nrows;
            if (ok) {
                int e0 = s_bnd[rl], e1 = s_bnd[rl + 1];
                for (int e = e0 + sub; e < e1; e += 4) {
                    int2 ed = __ldg(&g_edges[e]);
                    uint2 rv = s_rates[ed.x];
                    float2 lo = __half22float2(*(const __half2*)&rv.x);
                    float2 hi = __half22float2(*(const __half2*)&rv.y);
                    float w = __int_as_float(ed.y);
                    acc.x = fmaf(w, lo.x, acc.x);
                    acc.y = fmaf(w, lo.y, acc.y);
                    acc.z = fmaf(w, hi.x, acc.z);
                    acc.w = fmaf(w, hi.y, acc.w);
                }
            }
            acc.x += __shfl_down_sync(0xffffffffu, acc.x, 2);
            acc.y += __shfl_down_sync(0xffffffffu, acc.y, 2);
            acc.z += __shfl_down_sync(0xffffffffu, acc.z, 2);
            acc.w += __shfl_down_sync(0xffffffffu, acc.w, 2);
            acc.x += __shfl_down_sync(0xffffffffu, acc.x, 1);
            acc.y += __shfl_down_sync(0xffffffffu, acc.y, 1);
            acc.z += __shfl_down_sync(0xffffffffu, acc.z, 1);
            acc.w += __shfl_down_sync(0xffffffffu, acc.w, 1);
            if (ok && sub == 0) g_part[q][row0 + rl] = acc;
        }

        grid_barrier((unsigned)(2 * t + 1));            // all partials visible

        // ---- Phase B: combine partials + Euler update on owned rows ----
        if (myrow >= 0) {
            float4 p0 = ldcg_f4(&g_part[0][myrow]);
            float4 p1 = ldcg_f4(&g_part[1][myrow]);
            float4 p2 = ldcg_f4(&g_part[2][myrow]);
            float4 p3 = ldcg_f4(&g_part[3][myrow]);
            float4 s = make_float4(p0.x + p1.x + p2.x + p3.x,
                                   p0.y + p1.y + p2.y + p3.y,
                                   p0.z + p1.z + p2.z + p3.z,
                                   p0.w + p1.w + p2.w + p3.w);
            long long base = (long long)t * N_NODES + myrow;
            float4 vn;
            vn.x = v.x + my_a * (my_b + s.x + x[base         ] - v.x);
            vn.y = v.y + my_a * (my_b + s.y + x[base +    TN ] - v.y);
            vn.z = v.z + my_a * (my_b + s.z + x[base + 2*TN ] - v.z);
            vn.w = v.w + my_a * (my_b + s.w + x[base + 3*TN ] - v.w);
            v = vn;
            float4 r = make_float4(fmaxf(vn.x, 0.f), fmaxf(vn.y, 0.f),
                                   fmaxf(vn.z, 0.f), fmaxf(vn.w, 0.f));
            out[base         ] = r.x;
            out[base +    TN ] = r.y;
            out[base + 2*TN ] = r.z;
            out[base + 3*TN ] = r.w;
            __half2 h01 = __floats2half2_rn(r.x, r.y);
            __half2 h23 = __floats2half2_rn(r.z, r.w);
            g_ratebuf[(t + 1) & 1][myrow] =
                make_uint2(*(unsigned*)&h01, *(unsigned*)&h23);
        }

        if (t + 1 < T_STEPS) {
            grid_barrier((unsigned)(2 * t + 2));        // rates_{t+1} complete
            if (tid == 0) {                             // refill own quarter
                mbar_expect_tx(mbar, QTR_BYTES);
                bulk_g2s(sdest,
                         (const char*)&g_ratebuf[(t + 1) & 1][q * QTR],
                         QTR_BYTES, mbar);
            }
        }
    }
}

// ---------------- launch ----------------
extern "C" void kernel_launch(void* const* d_in, const int* in_sizes, int n_in,
                              void* d_out, int out_size) {
    const float* x    = (const float*)d_in[0];
    const float* bias = (const float*)d_in[1];
    const float* tau  = (const float*)d_in[2];
    const float* sign = (const float*)d_in[3];
    const float* cnt  = (const float*)d_in[4];
    const float* str  = (const float*)d_in[5];
    const int*   src  = (const int*)  d_in[6];
    const int*   tgt  = (const int*)  d_in[7];
    float*       out  = (float*)d_out;

    cudaFuncSetAttribute(persist_kernel,
                         cudaFuncAttributeMaxDynamicSharedMemorySize,
                         SMEM_TOTAL);

    init_kernel<<<(N_NODES + 255) / 256, 256>>>(bias, tau);
    hist_kernel<<<(N_EDGES + 255) / 256, 256>>>(src, tgt);
    scan_kernel<<<1, 1024>>>();
    sort_kernel<<<(N_EDGES + 255) / 256, 256>>>(src, tgt, sign, cnt, str);

    persist_kernel<<<NBLK, NTHR, SMEM_TOTAL>>>(x, out, bias);
}

// round 13
// speedup vs baseline: 1.6293x; 1.4889x over previous
#include <cuda_runtime.h>

#define N_NODES 50000
#define N_EDGES 1600000
#define N_EPAD  (N_EDGES + N_NODES)   // room for per-row even padding
#define BATCH   4
#define T_STEPS 50
#define DT      0.02f

// ---------------- static scratch (no allocations allowed) ----------------
__device__ int    g_hist[N_NODES];
__device__ int    g_row_start[N_NODES + 1];     // padded-even segments
__device__ int    g_cursor[N_NODES];
__device__ int4   g_epairs[N_EPAD / 2];         // 2 edges per int4 {s0,w0,s1,w1}
                                                // zero-init: pad slots stay w=0
__device__ float4 g_rates[2][N_NODES];          // ping-pong rate buffers
__device__ float4 g_v[N_NODES];                 // membrane state
__device__ float  g_alpha[N_NODES];

// ---------------- packed-math helpers ----------------
__device__ __forceinline__ void gather_fma(const float4* rp, float w,
                                           unsigned long long& a01,
                                           unsigned long long& a23) {
    unsigned long long r01, r23, ww;
    asm volatile("{\n\t"
        ".reg .f32 ra,rb,rc,rd;\n\t"
        "ld.global.nc.v4.f32 {ra,rb,rc,rd}, [%2];\n\t"
        "mov.b64 %0, {ra,rb};\n\t"
        "mov.b64 %1, {rc,rd};\n\t}"
        : "=l"(r01), "=l"(r23) : "l"(rp));
    asm("mov.b64 %0, {%1,%1};" : "=l"(ww) : "f"(w));
    asm("fma.rn.f32x2 %0, %1, %2, %0;" : "+l"(a01) : "l"(r01), "l"(ww));
    asm("fma.rn.f32x2 %0, %1, %2, %0;" : "+l"(a23) : "l"(r23), "l"(ww));
}

// ---------------- preprocessing ----------------

__global__ void init_kernel(const float* __restrict__ bias,
                            const float* __restrict__ tau) {
    int n = blockIdx.x * blockDim.x + threadIdx.x;
    if (n >= N_NODES) return;
    g_hist[n] = 0;
    float b = bias[n];
    g_v[n] = make_float4(b, b, b, b);
    float r = fmaxf(b, 0.0f);
    g_rates[0][n] = make_float4(r, r, r, r);
    float tt = fmaxf(tau[n], DT);
    g_alpha[n] = DT / tt;
}

__global__ void hist_kernel(const int* __restrict__ tgt) {
    int e = blockIdx.x * blockDim.x + threadIdx.x;
    if (e >= N_EDGES) return;
    atomicAdd(&g_hist[tgt[e]], 1);
}

// Exclusive scan over PADDED-EVEN degrees -> 16B-aligned pair segments
__global__ void scan_kernel() {
    __shared__ int s[1024];
    int tid = threadIdx.x;
    const int chunk = (N_NODES + 1023) / 1024;   // 49
    int beg = tid * chunk;
    int end = min(beg + chunk, N_NODES);
    int sum = 0;
    for (int i = beg; i < end; i++) sum += (g_hist[i] + 1) & ~1;
    s[tid] = sum;
    __syncthreads();
    for (int off = 1; off < 1024; off <<= 1) {
        int v = (tid >= off) ? s[tid - off] : 0;
        __syncthreads();
        s[tid] += v;
        __syncthreads();
    }
    int prefix = (tid > 0) ? s[tid - 1] : 0;
    for (int i = beg; i < end; i++) {
        g_row_start[i] = prefix;
        g_cursor[i]    = prefix;
        prefix += (g_hist[i] + 1) & ~1;
    }
    if (tid == 0) g_row_start[N_NODES] = s[1023];
}

// Counting-sort edges into padded CSR; pad slots remain zero-initialized.
__global__ void scatter_kernel(const int*   __restrict__ src,
                               const int*   __restrict__ tgt,
                               const float* __restrict__ sign,
                               const float* __restrict__ cnt,
                               const float* __restrict__ str) {
    int e = blockIdx.x * blockDim.x + threadIdx.x;
    if (e >= N_EDGES) return;
    float w = sign[e] * fmaxf(cnt[e], 0.0f) * fmaxf(str[e], 0.0f);
    int pos = atomicAdd(&g_cursor[tgt[e]], 1);
    ((int2*)g_epairs)[pos] = make_int2(src[e], __float_as_int(w));
}

// ---------------- hot loop: one kernel per timestep ----------------
// 8 lanes per row, 32 rows per 256-thread block. Each lane processes edge
// PAIRS (one LDG.128 record = 2 edges) with packed f32x2 FMA accumulation.
__global__ void __launch_bounds__(256)
step_kernel(const float* __restrict__ x,
            float*       __restrict__ out,
            const float* __restrict__ bias,
            int t, int parity) {
    __shared__ float s_acc[BATCH][32];

    int sub = threadIdx.x & 7;        // lane within 8-lane row group
    int grp = threadIdx.x >> 3;       // row group within block
    int row = blockIdx.x * 32 + grp;

    const float4* __restrict__ rin = g_rates[parity];

    unsigned long long a01 = 0ull, a23 = 0ull;   // packed {f32,f32} accumulators
    if (row < N_NODES) {
        int pbeg = g_row_start[row] >> 1;        // segments even => exact
        int pend = g_row_start[row + 1] >> 1;
        for (int p0 = pbeg; p0 < pend; p0 += 32) {
#pragma unroll
            for (int j = 0; j < 4; j++) {
                int pp = p0 + sub + 8 * j;
                if (pp < pend) {
                    int4 rec = __ldg(&g_epairs[pp]);
                    gather_fma(&rin[rec.x], __int_as_float(rec.y), a01, a23);
                    gather_fma(&rin[rec.z], __int_as_float(rec.w), a01, a23);
                }
            }
        }
    }
    float4 acc;
    asm("mov.b64 {%0,%1}, %2;" : "=f"(acc.x), "=f"(acc.y) : "l"(a01));
    asm("mov.b64 {%0,%1}, %2;" : "=f"(acc.z), "=f"(acc.w) : "l"(a23));

#pragma unroll
    for (int off = 4; off; off >>= 1) {
        acc.x += __shfl_down_sync(0xffffffffu, acc.x, off);
        acc.y += __shfl_down_sync(0xffffffffu, acc.y, off);
        acc.z += __shfl_down_sync(0xffffffffu, acc.z, off);
        acc.w += __shfl_down_sync(0xffffffffu, acc.w, off);
    }
    if (sub == 0) {
        s_acc[0][grp] = acc.x;
        s_acc[1][grp] = acc.y;
        s_acc[2][grp] = acc.z;
        s_acc[3][grp] = acc.w;
    }
    __syncthreads();

    // epilogue: 128 threads cover (batch, row) fully coalesced
    if (threadIdx.x < BATCH * 32) {
        int b = threadIdx.x >> 5;
        int r = threadIdx.x & 31;
        int row2 = blockIdx.x * 32 + r;
        if (row2 < N_NODES) {
            float a   = g_alpha[row2];
            float bs  = bias[row2];
            float ab  = s_acc[b][r];
            long long idx = (long long)(b * T_STEPS + t) * N_NODES + row2;
            float xv  = x[idx];
            float* vf = (float*)&g_v[row2];
            float v   = vf[b];
            float vn  = v + a * (bs + ab + xv - v);
            vf[b] = vn;
            float rl = fmaxf(vn, 0.f);
            float* routf = (float*)(g_rates[parity ^ 1]);
            routf[row2 * 4 + b] = rl;
            out[idx] = rl;
        }
    }
}

// ---------------- launch ----------------
extern "C" void kernel_launch(void* const* d_in, const int* in_sizes, int n_in,
                              void* d_out, int out_size) {
    const float* x    = (const float*)d_in[0];
    const float* bias = (const float*)d_in[1];
    const float* tau  = (const float*)d_in[2];
    const float* sign = (const float*)d_in[3];
    const float* cnt  = (const float*)d_in[4];
    const float* str  = (const float*)d_in[5];
    const int*   src  = (const int*)  d_in[6];
    const int*   tgt  = (const int*)  d_in[7];
    float*       out  = (float*)d_out;

    init_kernel<<<(N_NODES + 255) / 256, 256>>>(bias, tau);
    hist_kernel<<<(N_EDGES + 255) / 256, 256>>>(tgt);
    scan_kernel<<<1, 1024>>>();
    scatter_kernel<<<(N_EDGES + 255) / 256, 256>>>(src, tgt, sign, cnt, str);

    const int step_blocks = (N_NODES + 31) / 32;   // 1563
    for (int t = 0; t < T_STEPS; t++) {
        step_kernel<<<step_blocks, 256>>>(x, out, bias, t, t & 1);
    }
}